// round 9
// baseline (speedup 1.0000x reference)
#include <cuda_runtime.h>
#include <cstdint>
#include <cstddef>

// Problem constants
#define TT   2048
#define HH   2048
#define NE   16
#define TOPK 6
#define ID   1408
#define I2   2816
#define ISH  2816
#define IS2  5632
#define NSLOT (TT * TOPK)

// ---------------- scratch --------------------------------------------------
__device__ float g_buf1[(size_t)NSLOT * I2];   // 138 MB
__device__ float g_buf2[(size_t)NSLOT * ID];   //  69 MB
__device__ int   g_cnt [NE];
__device__ int   g_off [NE];
__device__ int   g_tok [NE * TT];
__device__ float g_wt  [NE * TT];

// ---------------- small kernels --------------------------------------------
__global__ void zero_cnt_kernel() {
    if (threadIdx.x < NE) g_cnt[threadIdx.x] = 0;
}

__global__ void prefix_kernel() {
    if (threadIdx.x == 0) {
        int acc = 0;
        for (int e = 0; e < NE; e++) { g_off[e] = acc; acc += g_cnt[e]; }
    }
}

__global__ void gate_kernel(const float* __restrict__ x,
                            const float* __restrict__ gw) {
    __shared__ float part[256];
    __shared__ float lg[NE];
    const int t   = blockIdx.x;
    const int tid = threadIdx.x;
    const int e   = tid & 15;
    const int c   = tid >> 4;

    const float* xr = x  + (size_t)t * HH;
    const float* wr = gw + (size_t)e * HH;
    float s = 0.f;
    const int h0 = c * 128;
#pragma unroll 8
    for (int h = h0; h < h0 + 128; h += 4) {
        float4 xv = *(const float4*)(xr + h);
        float4 wv = *(const float4*)(wr + h);
        s += xv.x * wv.x + xv.y * wv.y + xv.z * wv.z + xv.w * wv.w;
    }
    part[tid] = s;
    __syncthreads();
    if (tid < NE) {
        float tot = 0.f;
#pragma unroll
        for (int k = 0; k < 16; k++) tot += part[k * 16 + tid];
        lg[tid] = tot;
    }
    __syncthreads();
    if (tid == 0) {
        float mx = lg[0];
#pragma unroll
        for (int i = 1; i < NE; i++) mx = fmaxf(mx, lg[i]);
        float p[NE];
        float den = 0.f;
#pragma unroll
        for (int i = 0; i < NE; i++) { p[i] = expf(lg[i] - mx); den += p[i]; }
        const float inv = 1.f / den;
#pragma unroll
        for (int i = 0; i < NE; i++) p[i] *= inv;

        bool used[NE];
#pragma unroll
        for (int i = 0; i < NE; i++) used[i] = false;
        for (int j = 0; j < TOPK; j++) {
            int   be = 0;
            float bv = -1.f;
            for (int i = 0; i < NE; i++)
                if (!used[i] && p[i] > bv) { bv = p[i]; be = i; }
            used[be] = true;
            const int slot = atomicAdd(&g_cnt[be], 1);
            g_tok[be * TT + slot] = t;
            g_wt [be * TT + slot] = p[be];
        }
    }
}

__global__ void act_shared_kernel() {
    const int t = blockIdx.x;
    const float* row  = g_buf1 + (size_t)t * IS2;
    float*       orow = g_buf2 + (size_t)t * ISH;
    for (int i = threadIdx.x; i < ISH; i += blockDim.x) {
        const float g = row[i];
        const float u = row[i + ISH];
        orow[i] = u * g / (1.f + __expf(-g));
    }
}

__global__ void act_routed_kernel() {
    const int e = blockIdx.y;
    const int s = blockIdx.x;
    if (s >= g_cnt[e]) return;
    const float w = g_wt[e * TT + s];
    const size_t base = (size_t)(g_off[e] + s);
    const float* row  = g_buf1 + base * I2;
    float*       orow = g_buf2 + base * ID;
    for (int i = threadIdx.x; i < ID; i += blockDim.x) {
        const float g = row[i];
        const float u = row[i + ID];
        orow[i] = w * u * g / (1.f + __expf(-g));
    }
}

// ---------------- TF32 mma.sync GEMM:  C[M,N] = A[M,K] * B[N,K]^T -----------
// Block 128x128, 256 thr (8 warps, 2m x 4n), warp tile 64x32, KT=16.
// 4-stage cp.async pipeline: raw fp32 tiles in smem (pitch 20, bank-clean),
// cvt.rna -> tf32 at fragment-load time (same rounding + accumulation order
// as prior rounds -> identical numerics). Gather rows via cp.async src-size
// zero-fill. 80 KB dynamic smem, __launch_bounds__(256,2) -> 2 CTAs/SM.

__device__ __forceinline__ uint32_t tf32r(float f) {
    uint32_t u;
    asm("cvt.rna.tf32.f32 %0, %1;" : "=r"(u) : "f"(f));
    return u;
}

__device__ __forceinline__ void mma8(float* c, const uint32_t* a, const uint32_t* b) {
    asm volatile(
        "mma.sync.aligned.m16n8k8.row.col.f32.tf32.tf32.f32 "
        "{%0,%1,%2,%3},{%4,%5,%6,%7},{%8,%9},{%0,%1,%2,%3};"
        : "+f"(c[0]), "+f"(c[1]), "+f"(c[2]), "+f"(c[3])
        : "r"(a[0]), "r"(a[1]), "r"(a[2]), "r"(a[3]), "r"(b[0]), "r"(b[1]));
}

__device__ __forceinline__ void cp16(uint32_t dst, const void* src, int srcsz) {
    asm volatile("cp.async.ca.shared.global [%0], [%1], 16, %2;"
                 :: "r"(dst), "l"(src), "r"(srcsz) : "memory");
}

#define KT    16
#define PADW  20
#define STG   4
#define MB    128
#define NB    128
#define NTHR  256
#define TILE_WORDS (MB * PADW)            // per-stage words of one operand
#define TILE_BYTES (TILE_WORDS * 4)       // 10240
#define DSMEM_BYTES (2 * STG * TILE_BYTES)  // 81920

template <bool GATHER_A, bool SCATTER_C>
__device__ __forceinline__ void mma_core(
        const float* __restrict__ A, int lda,
        const float* __restrict__ B, int ldb,
        float* __restrict__ C, int ldc,
        int K, int M, const int* __restrict__ tl) {
    const int m0 = blockIdx.y * MB;
    if (m0 >= M) return;
    const int n0 = blockIdx.x * NB;

    extern __shared__ float dsm[];
    float* AsBase = dsm;                       // [STG][128][PADW]
    float* BsBase = dsm + STG * TILE_WORDS;    // [STG][128][PADW]

    const int tid  = threadIdx.x;
    const int lane = tid & 31;
    const int warp = tid >> 5;
    const int warp_m = (warp & 1) * 64;
    const int warp_n = (warp >> 1) * 32;

    // ---- staging map: 1 row per 2 threads, each thread 2 x 16B chunks -----
    const int srow = tid >> 1;               // 0..127
    const int c0   = (tid & 1) * 2;          // chunk base 0 or 2 (chunks of 4 floats)

    const int  rA = m0 + srow;
    const bool av = rA < M;
    int ar = 0;
    if (av) ar = GATHER_A ? tl[rA] : rA;
    const float* aPtr = A + (size_t)ar * lda + c0 * 4;
    const float* bPtr = B + (size_t)(n0 + srow) * ldb + c0 * 4;
    const int avsz = av ? 16 : 0;

    const uint32_t sA0 = (uint32_t)__cvta_generic_to_shared(AsBase + srow * PADW + c0 * 4);
    const uint32_t sB0 = (uint32_t)__cvta_generic_to_shared(BsBase + srow * PADW + c0 * 4);

    const int nkt = K / KT;

#define ISSUE(stage)                                                          \
    do {                                                                      \
        if ((stage) < nkt) {                                                  \
            const uint32_t so = (uint32_t)(((stage) & (STG - 1)) * TILE_BYTES); \
            const float* as_ = aPtr + (stage) * KT;                           \
            const float* bs_ = bPtr + (stage) * KT;                           \
            cp16(sA0 + so,      as_,     avsz);                               \
            cp16(sA0 + so + 16, as_ + 4, avsz);                               \
            cp16(sB0 + so,      bs_,     16);                                 \
            cp16(sB0 + so + 16, bs_ + 4, 16);                                 \
        }                                                                     \
        asm volatile("cp.async.commit_group;" ::: "memory");                  \
    } while (0)

    float acc[4][4][4];
#pragma unroll
    for (int mi = 0; mi < 4; mi++)
#pragma unroll
        for (int ni = 0; ni < 4; ni++)
#pragma unroll
            for (int i = 0; i < 4; i++) acc[mi][ni][i] = 0.f;

    const int q  = lane >> 2;
    const int kb = lane & 3;

    ISSUE(0); ISSUE(1); ISSUE(2);

    for (int kt = 0; kt < nkt; kt++) {
        asm volatile("cp.async.wait_group %0;" :: "n"(STG - 2) : "memory");
        __syncthreads();
        ISSUE(kt + STG - 1);

        const float* As = AsBase + (kt & (STG - 1)) * TILE_WORDS;
        const float* Bs = BsBase + (kt & (STG - 1)) * TILE_WORDS;

#pragma unroll
        for (int ks = 0; ks < KT; ks += 8) {
            uint32_t af[4][4];
#pragma unroll
            for (int mi = 0; mi < 4; mi++) {
                const int r = warp_m + mi * 16 + q;
                af[mi][0] = tf32r(As[r * PADW + ks + kb]);
                af[mi][1] = tf32r(As[(r + 8) * PADW + ks + kb]);
                af[mi][2] = tf32r(As[r * PADW + ks + kb + 4]);
                af[mi][3] = tf32r(As[(r + 8) * PADW + ks + kb + 4]);
            }
#pragma unroll
            for (int ni = 0; ni < 4; ni++) {
                const int rn = warp_n + ni * 8 + q;
                uint32_t bf[2] = { tf32r(Bs[rn * PADW + ks + kb]),
                                   tf32r(Bs[rn * PADW + ks + kb + 4]) };
#pragma unroll
                for (int mi = 0; mi < 4; mi++)
                    mma8(acc[mi][ni], af[mi], bf);
            }
        }
    }

    // epilogue: c0,c1 at (row, 2kb..2kb+1); c2,c3 at (row+8, same cols)
#pragma unroll
    for (int mi = 0; mi < 4; mi++) {
        const int rlo = m0 + warp_m + mi * 16 + q;
        const int rhi = rlo + 8;
#pragma unroll
        for (int ni = 0; ni < 4; ni++) {
            const int col = n0 + warp_n + ni * 8 + 2 * kb;
            if (rlo < M) {
                const int cr = SCATTER_C ? tl[rlo] : rlo;
                float* cp = C + (size_t)cr * ldc + col;
                if (SCATTER_C) {
                    atomicAdd(cp,     acc[mi][ni][0]);
                    atomicAdd(cp + 1, acc[mi][ni][1]);
                } else {
                    *(float2*)cp = make_float2(acc[mi][ni][0], acc[mi][ni][1]);
                }
            }
            if (rhi < M) {
                const int cr = SCATTER_C ? tl[rhi] : rhi;
                float* cp = C + (size_t)cr * ldc + col;
                if (SCATTER_C) {
                    atomicAdd(cp,     acc[mi][ni][2]);
                    atomicAdd(cp + 1, acc[mi][ni][3]);
                } else {
                    *(float2*)cp = make_float2(acc[mi][ni][2], acc[mi][ni][3]);
                }
            }
        }
    }
#undef ISSUE
}

// ---------------- GEMM wrappers ---------------------------------------------
__global__ void __launch_bounds__(NTHR, 2)
gemm_shared1(const float* __restrict__ x, const float* __restrict__ sw1) {
    mma_core<false, false>(x, HH, sw1, HH, g_buf1, IS2, HH, TT, nullptr);
}

__global__ void __launch_bounds__(NTHR, 2)
gemm_shared2(const float* __restrict__ sw2, float* __restrict__ out) {
    mma_core<false, false>(g_buf2, ISH, sw2, ISH, out, HH, ISH, TT, nullptr);
}

__global__ void __launch_bounds__(NTHR, 2)
gemm_routed1(const float* __restrict__ x, const float* __restrict__ w1) {
    const int e = blockIdx.z;
    mma_core<true, false>(
        x, HH,
        w1 + (size_t)e * I2 * HH, HH,
        g_buf1 + (size_t)g_off[e] * I2, I2,
        HH, g_cnt[e], g_tok + e * TT);
}

__global__ void __launch_bounds__(NTHR, 2)
gemm_routed2(const float* __restrict__ w2, float* __restrict__ out) {
    const int e = blockIdx.z;
    mma_core<false, true>(
        g_buf2 + (size_t)g_off[e] * ID, ID,
        w2 + (size_t)e * HH * ID, ID,
        out, HH,
        ID, g_cnt[e], g_tok + e * TT);
}

// ---------------- launcher --------------------------------------------------
extern "C" void kernel_launch(void* const* d_in, const int* in_sizes, int n_in,
                              void* d_out, int out_size) {
    const float* x   = (const float*)d_in[0];
    const float* gw  = (const float*)d_in[1];
    const float* w1  = (const float*)d_in[2];
    const float* w2  = (const float*)d_in[3];
    const float* sw1 = (const float*)d_in[4];
    const float* sw2 = (const float*)d_in[5];
    float* out = (float*)d_out;
    (void)in_sizes; (void)n_in; (void)out_size;

    cudaFuncSetAttribute(gemm_shared1, cudaFuncAttributeMaxDynamicSharedMemorySize, DSMEM_BYTES);
    cudaFuncSetAttribute(gemm_shared2, cudaFuncAttributeMaxDynamicSharedMemorySize, DSMEM_BYTES);
    cudaFuncSetAttribute(gemm_routed1, cudaFuncAttributeMaxDynamicSharedMemorySize, DSMEM_BYTES);
    cudaFuncSetAttribute(gemm_routed2, cudaFuncAttributeMaxDynamicSharedMemorySize, DSMEM_BYTES);

    // 1) routing
    zero_cnt_kernel<<<1, 32>>>();
    gate_kernel<<<TT, 256>>>(x, gw);
    prefix_kernel<<<1, 32>>>();

    // 2) shared FFN
    gemm_shared1<<<dim3(IS2 / NB, TT / MB, 1), NTHR, DSMEM_BYTES>>>(x, sw1);
    act_shared_kernel<<<TT, 256>>>();
    gemm_shared2<<<dim3(HH / NB, TT / MB, 1), NTHR, DSMEM_BYTES>>>(sw2, out);

    // 3) routed path
    gemm_routed1<<<dim3(I2 / NB, TT / MB, NE), NTHR, DSMEM_BYTES>>>(x, w1);
    act_routed_kernel<<<dim3(TT, NE), 256>>>();
    gemm_routed2<<<dim3(HH / NB, TT / MB, NE), NTHR, DSMEM_BYTES>>>(w2, out);
}

// round 10
// speedup vs baseline: 1.0624x; 1.0624x over previous
#include <cuda_runtime.h>
#include <cstdint>
#include <cstddef>

// Problem constants
#define TT   2048
#define HH   2048
#define NE   16
#define TOPK 6
#define ID   1408
#define I2   2816
#define ISH  2816
#define IS2  5632
#define NSLOT (TT * TOPK)

// ---------------- scratch --------------------------------------------------
__device__ float g_buf1[(size_t)NSLOT * I2];   // 138 MB
__device__ float g_buf2[(size_t)NSLOT * ID];   //  69 MB
__device__ int   g_cnt [NE];
__device__ int   g_off [NE];
__device__ int   g_tok [NE * TT];
__device__ float g_wt  [NE * TT];

// ---------------- small kernels --------------------------------------------
__global__ void zero_cnt_kernel() {
    if (threadIdx.x < NE) g_cnt[threadIdx.x] = 0;
}

__global__ void prefix_kernel() {
    if (threadIdx.x == 0) {
        int acc = 0;
        for (int e = 0; e < NE; e++) { g_off[e] = acc; acc += g_cnt[e]; }
    }
}

__global__ void gate_kernel(const float* __restrict__ x,
                            const float* __restrict__ gw) {
    __shared__ float part[256];
    __shared__ float lg[NE];
    const int t   = blockIdx.x;
    const int tid = threadIdx.x;
    const int e   = tid & 15;
    const int c   = tid >> 4;

    const float* xr = x  + (size_t)t * HH;
    const float* wr = gw + (size_t)e * HH;
    float s = 0.f;
    const int h0 = c * 128;
#pragma unroll 8
    for (int h = h0; h < h0 + 128; h += 4) {
        float4 xv = *(const float4*)(xr + h);
        float4 wv = *(const float4*)(wr + h);
        s += xv.x * wv.x + xv.y * wv.y + xv.z * wv.z + xv.w * wv.w;
    }
    part[tid] = s;
    __syncthreads();
    if (tid < NE) {
        float tot = 0.f;
#pragma unroll
        for (int k = 0; k < 16; k++) tot += part[k * 16 + tid];
        lg[tid] = tot;
    }
    __syncthreads();
    if (tid == 0) {
        float mx = lg[0];
#pragma unroll
        for (int i = 1; i < NE; i++) mx = fmaxf(mx, lg[i]);
        float p[NE];
        float den = 0.f;
#pragma unroll
        for (int i = 0; i < NE; i++) { p[i] = expf(lg[i] - mx); den += p[i]; }
        const float inv = 1.f / den;
#pragma unroll
        for (int i = 0; i < NE; i++) p[i] *= inv;

        bool used[NE];
#pragma unroll
        for (int i = 0; i < NE; i++) used[i] = false;
        for (int j = 0; j < TOPK; j++) {
            int   be = 0;
            float bv = -1.f;
            for (int i = 0; i < NE; i++)
                if (!used[i] && p[i] > bv) { bv = p[i]; be = i; }
            used[be] = true;
            const int slot = atomicAdd(&g_cnt[be], 1);
            g_tok[be * TT + slot] = t;
            g_wt [be * TT + slot] = p[be];
        }
    }
}

__global__ void act_shared_kernel() {
    const int t = blockIdx.x;
    const float* row  = g_buf1 + (size_t)t * IS2;
    float*       orow = g_buf2 + (size_t)t * ISH;
    for (int i = threadIdx.x; i < ISH; i += blockDim.x) {
        const float g = row[i];
        const float u = row[i + ISH];
        orow[i] = u * g / (1.f + __expf(-g));
    }
}

__global__ void act_routed_kernel() {
    const int e = blockIdx.y;
    const int s = blockIdx.x;
    if (s >= g_cnt[e]) return;
    const float w = g_wt[e * TT + s];
    const size_t base = (size_t)(g_off[e] + s);
    const float* row  = g_buf1 + base * I2;
    float*       orow = g_buf2 + base * ID;
    for (int i = threadIdx.x; i < ID; i += blockDim.x) {
        const float g = row[i];
        const float u = row[i + ID];
        orow[i] = w * u * g / (1.f + __expf(-g));
    }
}

// ---------------- TF32 mma.sync GEMM:  C[M,N] = A[M,K] * B[N,K]^T -----------
// R5 skeleton (block 128x128, 256 thr, 8 warps 2m x 4n, warp tile 64x32,
// KT=16 double-buffered, cvt.rna at staging) + R7 LDS.64 fragment layout:
// smem rows are 16 words = 8 dword slots; k -> slot d(k)=(k&3)+4*(k>>3),
// word (k>>2)&1, so (k,k+4) are one aligned 8B slot; slot index XORed with
// s(r)=((r>>1)&1)<<2 | ((r>>2)&1)<<1 (bank-verified in R7). Halves fragment
// LDS instruction count (48 -> 24 per warp per KT) at identical numerics.

__device__ __forceinline__ uint32_t tf32r(float f) {
    uint32_t u;
    asm("cvt.rna.tf32.f32 %0, %1;" : "=r"(u) : "f"(f));
    return u;
}

__device__ __forceinline__ void mma8(float* c, const uint32_t* a, const uint32_t* b) {
    asm volatile(
        "mma.sync.aligned.m16n8k8.row.col.f32.tf32.tf32.f32 "
        "{%0,%1,%2,%3},{%4,%5,%6,%7},{%8,%9},{%0,%1,%2,%3};"
        : "+f"(c[0]), "+f"(c[1]), "+f"(c[2]), "+f"(c[3])
        : "r"(a[0]), "r"(a[1]), "r"(a[2]), "r"(a[3]), "r"(b[0]), "r"(b[1]));
}

__device__ __forceinline__ int swz_s(int r) {
    return ((((r) >> 1) & 1) << 2) | ((((r) >> 2) & 1) << 1);
}

#define KT   16
#define MB   128
#define NB   128
#define NTHR 256

template <bool GATHER_A, bool SCATTER_C>
__device__ __forceinline__ void mma_core(
        const float* __restrict__ A, int lda,
        const float* __restrict__ B, int ldb,
        float* __restrict__ C, int ldc,
        int K, int M, const int* __restrict__ tl) {
    const int m0 = blockIdx.y * MB;
    if (m0 >= M) return;
    const int n0 = blockIdx.x * NB;

    __shared__ uint32_t As[2][MB][KT];   // 16 KB
    __shared__ uint32_t Bs[2][NB][KT];   // 16 KB

    const int tid  = threadIdx.x;
    const int lane = tid & 31;
    const int warp = tid >> 5;
    const int warp_m = (warp & 1) * 64;   // 2 warps along M
    const int warp_n = (warp >> 1) * 32;  // 4 warps along N

    // ---- staging: 2 threads per row; thread g covers k-half [8g, 8g+8) ----
    const int srow = tid >> 1;            // 0..127
    const int g    = tid & 1;
    const int kb8  = g * 8;

    const int  rA = m0 + srow;
    const bool av = rA < M;
    int ar = 0;
    if (av) ar = GATHER_A ? tl[rA] : rA;
    const float* aPtr = A + (size_t)ar * lda + kb8;
    const float* bPtr = B + (size_t)(n0 + srow) * ldb + kb8;
    const int sS = swz_s(srow);

    float4 ra0, ra1, rb0, rb1;

#define LDG_TILE(kt)                                                       \
    do {                                                                   \
        const int k0_ = (kt) * KT;                                         \
        ra0 = av ? *(const float4*)(aPtr + k0_)                            \
                 : make_float4(0.f, 0.f, 0.f, 0.f);                        \
        ra1 = av ? *(const float4*)(aPtr + k0_ + 4)                        \
                 : make_float4(0.f, 0.f, 0.f, 0.f);                        \
        rb0 = *(const float4*)(bPtr + k0_);                                \
        rb1 = *(const float4*)(bPtr + k0_ + 4);                            \
    } while (0)

    // word0 of slot = value at k, word1 = value at k+4
#define STS_TILE(buf)                                                      \
    do {                                                                   \
        const float* a0_ = &ra0.x;                                         \
        const float* a1_ = &ra1.x;                                         \
        const float* b0_ = &rb0.x;                                         \
        const float* b1_ = &rb1.x;                                         \
        _Pragma("unroll")                                                  \
        for (int j = 0; j < 4; j++) {                                      \
            const int dw = (j + 4 * g) ^ sS;                               \
            *(uint2*)&As[buf][srow][2 * dw] =                              \
                make_uint2(tf32r(a0_[j]), tf32r(a1_[j]));                  \
            *(uint2*)&Bs[buf][srow][2 * dw] =                              \
                make_uint2(tf32r(b0_[j]), tf32r(b1_[j]));                  \
        }                                                                  \
    } while (0)

    float acc[4][4][4];
#pragma unroll
    for (int mi = 0; mi < 4; mi++)
#pragma unroll
        for (int ni = 0; ni < 4; ni++)
#pragma unroll
            for (int i = 0; i < 4; i++) acc[mi][ni][i] = 0.f;

    const int q  = lane >> 2;
    const int kb = lane & 3;
    const int sq = swz_s(q);   // s() ignores bit 3+, so same for r, r+8, all mi/ni
    const int colH[2] = { 2 * ((kb    ) ^ sq),     // k-half 0 (k=kb, kb+4)
                          2 * ((kb + 4) ^ sq) };   // k-half 1 (k=kb+8, kb+12)

    LDG_TILE(0);
    STS_TILE(0);
    __syncthreads();

    const int nkt = K / KT;
    for (int kt = 0; kt < nkt; kt++) {
        const int cur = kt & 1;
        const bool more = (kt + 1 < nkt);
        if (more) LDG_TILE(kt + 1);

#pragma unroll
        for (int h = 0; h < 2; h++) {
            const int col = colH[h];
            uint32_t af[4][4];
#pragma unroll
            for (int mi = 0; mi < 4; mi++) {
                const int r = warp_m + mi * 16 + q;
                const uint2 lo = *(const uint2*)&As[cur][r    ][col];  // (a0,a2)
                const uint2 hi = *(const uint2*)&As[cur][r + 8][col];  // (a1,a3)
                af[mi][0] = lo.x; af[mi][1] = hi.x;
                af[mi][2] = lo.y; af[mi][3] = hi.y;
            }
#pragma unroll
            for (int ni = 0; ni < 4; ni++) {
                const int rn = warp_n + ni * 8 + q;
                const uint2 bv = *(const uint2*)&Bs[cur][rn][col];
                uint32_t bf[2] = { bv.x, bv.y };
#pragma unroll
                for (int mi = 0; mi < 4; mi++)
                    mma8(acc[mi][ni], af[mi], bf);
            }
        }

        if (more) STS_TILE(cur ^ 1);
        __syncthreads();
    }

    // epilogue: c0,c1 at (row, 2kb..2kb+1); c2,c3 at (row+8, same cols)
#pragma unroll
    for (int mi = 0; mi < 4; mi++) {
        const int rlo = m0 + warp_m + mi * 16 + q;
        const int rhi = rlo + 8;
#pragma unroll
        for (int ni = 0; ni < 4; ni++) {
            const int col = n0 + warp_n + ni * 8 + 2 * kb;
            if (rlo < M) {
                const int cr = SCATTER_C ? tl[rlo] : rlo;
                float* cp = C + (size_t)cr * ldc + col;
                if (SCATTER_C) {
                    atomicAdd(cp,     acc[mi][ni][0]);
                    atomicAdd(cp + 1, acc[mi][ni][1]);
                } else {
                    *(float2*)cp = make_float2(acc[mi][ni][0], acc[mi][ni][1]);
                }
            }
            if (rhi < M) {
                const int cr = SCATTER_C ? tl[rhi] : rhi;
                float* cp = C + (size_t)cr * ldc + col;
                if (SCATTER_C) {
                    atomicAdd(cp,     acc[mi][ni][2]);
                    atomicAdd(cp + 1, acc[mi][ni][3]);
                } else {
                    *(float2*)cp = make_float2(acc[mi][ni][2], acc[mi][ni][3]);
                }
            }
        }
    }
#undef LDG_TILE
#undef STS_TILE
}

// ---------------- GEMM wrappers ---------------------------------------------
__global__ void __launch_bounds__(NTHR, 2)
gemm_shared1(const float* __restrict__ x, const float* __restrict__ sw1) {
    mma_core<false, false>(x, HH, sw1, HH, g_buf1, IS2, HH, TT, nullptr);
}

__global__ void __launch_bounds__(NTHR, 2)
gemm_shared2(const float* __restrict__ sw2, float* __restrict__ out) {
    mma_core<false, false>(g_buf2, ISH, sw2, ISH, out, HH, ISH, TT, nullptr);
}

__global__ void __launch_bounds__(NTHR, 2)
gemm_routed1(const float* __restrict__ x, const float* __restrict__ w1) {
    const int e = blockIdx.z;
    mma_core<true, false>(
        x, HH,
        w1 + (size_t)e * I2 * HH, HH,
        g_buf1 + (size_t)g_off[e] * I2, I2,
        HH, g_cnt[e], g_tok + e * TT);
}

__global__ void __launch_bounds__(NTHR, 2)
gemm_routed2(const float* __restrict__ w2, float* __restrict__ out) {
    const int e = blockIdx.z;
    mma_core<false, true>(
        g_buf2 + (size_t)g_off[e] * ID, ID,
        w2 + (size_t)e * HH * ID, ID,
        out, HH,
        ID, g_cnt[e], g_tok + e * TT);
}

// ---------------- launcher --------------------------------------------------
extern "C" void kernel_launch(void* const* d_in, const int* in_sizes, int n_in,
                              void* d_out, int out_size) {
    const float* x   = (const float*)d_in[0];
    const float* gw  = (const float*)d_in[1];
    const float* w1  = (const float*)d_in[2];
    const float* w2  = (const float*)d_in[3];
    const float* sw1 = (const float*)d_in[4];
    const float* sw2 = (const float*)d_in[5];
    float* out = (float*)d_out;
    (void)in_sizes; (void)n_in; (void)out_size;

    // 1) routing
    zero_cnt_kernel<<<1, 32>>>();
    gate_kernel<<<TT, 256>>>(x, gw);
    prefix_kernel<<<1, 32>>>();

    // 2) shared FFN
    gemm_shared1<<<dim3(IS2 / NB, TT / MB, 1), NTHR>>>(x, sw1);
    act_shared_kernel<<<TT, 256>>>();
    gemm_shared2<<<dim3(HH / NB, TT / MB, 1), NTHR>>>(sw2, out);

    // 3) routed path
    gemm_routed1<<<dim3(I2 / NB, TT / MB, NE), NTHR>>>(x, w1);
    act_routed_kernel<<<dim3(TT, NE), 256>>>();
    gemm_routed2<<<dim3(HH / NB, TT / MB, NE), NTHR>>>(w2, out);
}

// round 14
// speedup vs baseline: 1.6014x; 1.5073x over previous
#include <cuda_runtime.h>
#include <cuda_fp16.h>
#include <cstdint>
#include <cstddef>

// Problem shape
#define TT   2048
#define HH   2048
#define NE   16
#define TOPK 6
#define ID   1408
#define I2   2816
#define ISH  2816
#define IS2  5632
#define NSLOT (TT * TOPK)

// ---------------- device scratch (touched only from device code) -----------
__device__ float sc_up  [(size_t)NSLOT * I2];   // 138 MB: gate_up (routed; head = shared)
__device__ float sc_act [(size_t)NSLOT * ID];   //  69 MB: activations
__device__ int   sc_cnt [NE];
__device__ int   sc_base[NE];
__device__ int   sc_tok [NE * TT];
__device__ float sc_prob[NE * TT];

// ---------------- routing kernels ------------------------------------------
__global__ void k_reset() {
    if (threadIdx.x < NE) sc_cnt[threadIdx.x] = 0;
}

__global__ void k_scan() {
    if (threadIdx.x == 0) {
        int a = 0;
        for (int e = 0; e < NE; e++) { sc_base[e] = a; a += sc_cnt[e]; }
    }
}

__global__ void k_gate(const float* __restrict__ x,
                       const float* __restrict__ gw) {
    __shared__ float red[256];
    __shared__ float lg[NE];
    const int t   = blockIdx.x;
    const int tid = threadIdx.x;
    const int e   = tid & 15;
    const int seg = tid >> 4;

    const float* xr = x  + (size_t)t * HH;
    const float* wr = gw + (size_t)e * HH;
    float s = 0.f;
    const int h0 = seg * 128;
#pragma unroll 8
    for (int h = h0; h < h0 + 128; h += 4) {
        float4 a = *(const float4*)(xr + h);
        float4 b = *(const float4*)(wr + h);
        s += a.x * b.x + a.y * b.y + a.z * b.z + a.w * b.w;
    }
    red[tid] = s;
    __syncthreads();
    if (tid < NE) {
        float tot = 0.f;
#pragma unroll
        for (int k = 0; k < 16; k++) tot += red[k * 16 + tid];
        lg[tid] = tot;
    }
    __syncthreads();
    if (tid == 0) {
        float mx = lg[0];
#pragma unroll
        for (int i = 1; i < NE; i++) mx = fmaxf(mx, lg[i]);
        float p[NE];
        float den = 0.f;
#pragma unroll
        for (int i = 0; i < NE; i++) { p[i] = expf(lg[i] - mx); den += p[i]; }
        const float inv = 1.f / den;
#pragma unroll
        for (int i = 0; i < NE; i++) p[i] *= inv;

        bool taken[NE];
#pragma unroll
        for (int i = 0; i < NE; i++) taken[i] = false;
        for (int j = 0; j < TOPK; j++) {
            int   be = 0;
            float bv = -1.f;
            for (int i = 0; i < NE; i++)
                if (!taken[i] && p[i] > bv) { bv = p[i]; be = i; }
            taken[be] = true;
            const int slot = atomicAdd(&sc_cnt[be], 1);
            sc_tok [be * TT + slot] = t;
            sc_prob[be * TT + slot] = p[be];
        }
    }
}

// ---------------- activation kernels ----------------------------------------
__global__ void k_silu_shared() {
    const int t = blockIdx.x;
    const float* r = sc_up  + (size_t)t * IS2;
    float*       o = sc_act + (size_t)t * ISH;
    for (int i = threadIdx.x; i < ISH; i += blockDim.x) {
        const float g = r[i];
        const float u = r[i + ISH];
        o[i] = u * g / (1.f + __expf(-g));
    }
}

__global__ void k_silu_routed() {
    const int e = blockIdx.y;
    const int s = blockIdx.x;
    if (s >= sc_cnt[e]) return;
    const float w = sc_prob[e * TT + s];
    const size_t slot = (size_t)(sc_base[e] + s);
    const float* r = sc_up  + slot * I2;
    float*       o = sc_act + slot * ID;
    for (int i = threadIdx.x; i < ID; i += blockDim.x) {
        const float g = r[i];
        const float u = r[i + ID];
        o[i] = w * u * g / (1.f + __expf(-g));
    }
}

// ---------------- FP16 tensor-core GEMM  C[M,N] = A[M,K] * B[N,K]^T ---------
// m16n8k16 fp16 (11-bit mantissa == tf32) with fp32 accumulate. Block
// 128x128, 8 warps (2m x 4n), warp tile 64x32, KT=32 halves double-buffered
// (32 KB). Tiles [row][k] fp16; 64B rows as 4 x 16B kgroups swizzled
// kg ^ ((row>>1)&3). Fragments via ldmatrix.x4. f32->f16 RN at staging.

__device__ __forceinline__ uint32_t packh2(float lo, float hi) {
    __half2 h = __floats2half2_rn(lo, hi);
    return *reinterpret_cast<uint32_t*>(&h);
}

__device__ __forceinline__ void hmma(float* c, const uint32_t* a, const uint32_t* b) {
    asm volatile(
        "mma.sync.aligned.m16n8k16.row.col.f32.f16.f16.f32 "
        "{%0,%1,%2,%3},{%4,%5,%6,%7},{%8,%9},{%0,%1,%2,%3};"
        : "+f"(c[0]), "+f"(c[1]), "+f"(c[2]), "+f"(c[3])
        : "r"(a[0]), "r"(a[1]), "r"(a[2]), "r"(a[3]), "r"(b[0]), "r"(b[1]));
}

__device__ __forceinline__ void ldmx4(uint32_t* r, uint32_t addr) {
    asm volatile(
        "ldmatrix.sync.aligned.m8n8.x4.shared.b16 {%0,%1,%2,%3}, [%4];"
        : "=r"(r[0]), "=r"(r[1]), "=r"(r[2]), "=r"(r[3]) : "r"(addr));
}

#define KT    32
#define BM    128
#define BN    128
#define NTH   256
#define ROWB  64
#define TILEB (BM * ROWB)

template <bool GATH, bool SCAT>
__device__ __forceinline__ void gemm_body(
        const float* __restrict__ A, int lda,
        const float* __restrict__ B, int ldb,
        float* __restrict__ C, int ldc,
        int K, int M, const int* __restrict__ lst) {
    const int m0 = blockIdx.y * BM;
    if (m0 >= M) return;
    const int n0 = blockIdx.x * BN;

    __shared__ uint8_t sh[4 * TILEB];   // A0 A1 B0 B1
    const uint32_t sb = (uint32_t)__cvta_generic_to_shared(sh);

    const int tid  = threadIdx.x;
    const int lane = tid & 31;
    const int wrp  = tid >> 5;
    const int wm = (wrp & 1) * 64;
    const int wn = (wrp >> 1) * 32;

    // staging: row = tid>>1, k-half = (tid&1)*16 halves
    const int srow = tid >> 1;
    const int kh16 = (tid & 1) * 16;
    const int kg0  = (tid & 1) * 2;
    const int ssw  = (srow >> 1) & 3;

    const int  rA = m0 + srow;
    const bool ok = rA < M;
    int ar = 0;
    if (ok) ar = GATH ? lst[rA] : rA;
    const float* ap = A + (size_t)ar * lda + kh16;
    const float* bp = B + (size_t)(n0 + srow) * ldb + kh16;

    const uint32_t wA0 = sb + srow * ROWB + (((kg0    ) ^ ssw) << 4);
    const uint32_t wA1 = sb + srow * ROWB + (((kg0 + 1) ^ ssw) << 4);
    const uint32_t wB0 = wA0 + 2 * TILEB;
    const uint32_t wB1 = wA1 + 2 * TILEB;

    float4 qa0, qa1, qa2, qa3, qb0, qb1, qb2, qb3;

#define FETCH(kt)                                                           \
    do {                                                                    \
        const int kk = (kt) * KT;                                           \
        if (ok) {                                                           \
            qa0 = *(const float4*)(ap + kk);                                \
            qa1 = *(const float4*)(ap + kk + 4);                            \
            qa2 = *(const float4*)(ap + kk + 8);                            \
            qa3 = *(const float4*)(ap + kk + 12);                           \
        } else {                                                            \
            qa0 = qa1 = qa2 = qa3 = make_float4(0.f, 0.f, 0.f, 0.f);        \
        }                                                                   \
        qb0 = *(const float4*)(bp + kk);                                    \
        qb1 = *(const float4*)(bp + kk + 4);                                \
        qb2 = *(const float4*)(bp + kk + 8);                                \
        qb3 = *(const float4*)(bp + kk + 12);                               \
    } while (0)

#define STORE(buf)                                                          \
    do {                                                                    \
        const uint32_t d_ = (buf) * TILEB;                                  \
        asm volatile("st.shared.v4.b32 [%0], {%1,%2,%3,%4};" ::             \
            "r"(wA0 + d_), "r"(packh2(qa0.x, qa0.y)),                       \
            "r"(packh2(qa0.z, qa0.w)), "r"(packh2(qa1.x, qa1.y)),           \
            "r"(packh2(qa1.z, qa1.w)) : "memory");                          \
        asm volatile("st.shared.v4.b32 [%0], {%1,%2,%3,%4};" ::             \
            "r"(wA1 + d_), "r"(packh2(qa2.x, qa2.y)),                       \
            "r"(packh2(qa2.z, qa2.w)), "r"(packh2(qa3.x, qa3.y)),           \
            "r"(packh2(qa3.z, qa3.w)) : "memory");                          \
        asm volatile("st.shared.v4.b32 [%0], {%1,%2,%3,%4};" ::             \
            "r"(wB0 + d_), "r"(packh2(qb0.x, qb0.y)),                       \
            "r"(packh2(qb0.z, qb0.w)), "r"(packh2(qb1.x, qb1.y)),           \
            "r"(packh2(qb1.z, qb1.w)) : "memory");                          \
        asm volatile("st.shared.v4.b32 [%0], {%1,%2,%3,%4};" ::             \
            "r"(wB1 + d_), "r"(packh2(qb2.x, qb2.y)),                       \
            "r"(packh2(qb2.z, qb2.w)), "r"(packh2(qb3.x, qb3.y)),           \
            "r"(packh2(qb3.z, qb3.w)) : "memory");                          \
    } while (0)

    float acc[4][4][4];
#pragma unroll
    for (int mi = 0; mi < 4; mi++)
#pragma unroll
        for (int ni = 0; ni < 4; ni++)
#pragma unroll
            for (int i = 0; i < 4; i++) acc[mi][ni][i] = 0.f;

    // fragment address precompute
    const int rFA = wm + (lane & 15);
    const int swA = (rFA >> 1) & 3;
    const int hiA = lane >> 4;
    const int rFB = wn + ((lane >> 4) << 3) + (lane & 7);
    const int swB = (rFB >> 1) & 3;
    const int seB = (lane >> 3) & 1;

    const int q  = lane >> 2;
    const int kb = lane & 3;

    FETCH(0);
    STORE(0);
    __syncthreads();

    const int nkt = K / KT;
    for (int kt = 0; kt < nkt; kt++) {
        const int cur = kt & 1;
        const bool more = (kt + 1 < nkt);
        if (more) FETCH(kt + 1);

        const uint32_t bA = sb + cur * TILEB;
        const uint32_t bB = sb + (2 + cur) * TILEB;

#pragma unroll
        for (int s = 0; s < 2; s++) {
            uint32_t fa[4][4], fb[2][4];
#pragma unroll
            for (int mi = 0; mi < 4; mi++)
                ldmx4(fa[mi], bA + (rFA + mi * 16) * ROWB
                              + (((2 * s + hiA) ^ swA) << 4));
#pragma unroll
            for (int j = 0; j < 2; j++)
                ldmx4(fb[j], bB + (rFB + 16 * j) * ROWB
                             + (((2 * s + seB) ^ swB) << 4));
#pragma unroll
            for (int mi = 0; mi < 4; mi++)
#pragma unroll
                for (int ni = 0; ni < 4; ni++) {
                    uint32_t bb[2] = { (ni & 1) ? fb[ni >> 1][2] : fb[ni >> 1][0],
                                       (ni & 1) ? fb[ni >> 1][3] : fb[ni >> 1][1] };
                    hmma(acc[mi][ni], fa[mi], bb);
                }
        }

        if (more) STORE(cur ^ 1);
        __syncthreads();
    }

    // epilogue
#pragma unroll
    for (int mi = 0; mi < 4; mi++) {
        const int rlo = m0 + wm + mi * 16 + q;
        const int rhi = rlo + 8;
#pragma unroll
        for (int ni = 0; ni < 4; ni++) {
            const int col = n0 + wn + ni * 8 + 2 * kb;
            if (rlo < M) {
                const int cr = SCAT ? lst[rlo] : rlo;
                float* cp = C + (size_t)cr * ldc + col;
                if (SCAT) {
                    atomicAdd(cp,     acc[mi][ni][0]);
                    atomicAdd(cp + 1, acc[mi][ni][1]);
                } else {
                    *(float2*)cp = make_float2(acc[mi][ni][0], acc[mi][ni][1]);
                }
            }
            if (rhi < M) {
                const int cr = SCAT ? lst[rhi] : rhi;
                float* cp = C + (size_t)cr * ldc + col;
                if (SCAT) {
                    atomicAdd(cp,     acc[mi][ni][2]);
                    atomicAdd(cp + 1, acc[mi][ni][3]);
                } else {
                    *(float2*)cp = make_float2(acc[mi][ni][2], acc[mi][ni][3]);
                }
            }
        }
    }
#undef FETCH
#undef STORE
}

// ---------------- GEMM entry points -----------------------------------------
__global__ void __launch_bounds__(NTH, 2)
k_ffn_up(const float* __restrict__ x, const float* __restrict__ sw1) {
    gemm_body<false, false>(x, HH, sw1, HH, sc_up, IS2, HH, TT, nullptr);
}

__global__ void __launch_bounds__(NTH, 2)
k_ffn_down(const float* __restrict__ sw2, float* __restrict__ out) {
    gemm_body<false, false>(sc_act, ISH, sw2, ISH, out, HH, ISH, TT, nullptr);
}

__global__ void __launch_bounds__(NTH, 2)
k_moe_up(const float* __restrict__ x, const float* __restrict__ w1) {
    const int e = blockIdx.z;
    gemm_body<true, false>(
        x, HH,
        w1 + (size_t)e * I2 * HH, HH,
        sc_up + (size_t)sc_base[e] * I2, I2,
        HH, sc_cnt[e], sc_tok + e * TT);
}

__global__ void __launch_bounds__(NTH, 2)
k_moe_down(const float* __restrict__ w2, float* __restrict__ out) {
    const int e = blockIdx.z;
    gemm_body<false, true>(
        sc_act + (size_t)sc_base[e] * ID, ID,
        w2 + (size_t)e * HH * ID, ID,
        out, HH,
        ID, sc_cnt[e], sc_tok + e * TT);
}

// ---------------- launcher (kernel launches only) ---------------------------
extern "C" void kernel_launch(void* const* d_in, const int* in_sizes, int n_in,
                              void* d_out, int out_size) {
    const float* x   = (const float*)d_in[0];
    const float* gw  = (const float*)d_in[1];
    const float* w1  = (const float*)d_in[2];
    const float* w2  = (const float*)d_in[3];
    const float* sw1 = (const float*)d_in[4];
    const float* sw2 = (const float*)d_in[5];
    float* out = (float*)d_out;
    (void)in_sizes; (void)n_in; (void)out_size;

    k_reset<<<1, 32>>>();
    k_gate<<<TT, 256>>>(x, gw);
    k_scan<<<1, 32>>>();

    k_ffn_up<<<dim3(IS2 / BN, TT / BM, 1), NTH>>>(x, sw1);
    k_silu_shared<<<TT, 256>>>();
    k_ffn_down<<<dim3(HH / BN, TT / BM, 1), NTH>>>(sw2, out);

    k_moe_up<<<dim3(I2 / BN, TT / BM, NE), NTH>>>(x, w1);
    k_silu_routed<<<dim3(TT, NE), 256>>>();
    k_moe_down<<<dim3(HH / BN, TT / BM, NE), NTH>>>(w2, out);
}

// round 16
// speedup vs baseline: 2.1289x; 1.3294x over previous
#include <cuda_runtime.h>
#include <cuda_fp16.h>
#include <cstdint>
#include <cstddef>

// Problem shape
#define TT   2048
#define HH   2048
#define NE   16
#define TOPK 6
#define ID   1408
#define I2   2816
#define ISH  2816
#define IS2  5632
#define NSLOT (TT * TOPK)

// ---------------- device scratch -------------------------------------------
__device__ float  sc_up  [(size_t)NSLOT * I2];    // 138 MB fp32 gate_up (head = shared phase)
__device__ __half sc_acth[(size_t)NSLOT * ID];    // 34.6 MB fp16 activations (head = shared)
__device__ __half sc_xh  [(size_t)TT * HH];       //  8.4 MB
__device__ __half sc_w1h [(size_t)NE * I2 * HH];  // 184.5 MB
__device__ __half sc_w2h [(size_t)NE * HH * ID];  //  92.3 MB
__device__ __half sc_sw1h[(size_t)IS2 * HH];      //  23.1 MB
__device__ __half sc_sw2h[(size_t)HH * ISH];      //  11.5 MB
__device__ int    sc_cnt [NE];
__device__ int    sc_base[NE];
__device__ int    sc_tok [NE * TT];
__device__ float  sc_prob[NE * TT];

// ---------------- f32 -> f16 conversion (grid-stride, 4 elems/thread) ------
__global__ void k_cvt(const float* __restrict__ src, __half* __restrict__ dst,
                      int n4) {
    const int stride = gridDim.x * blockDim.x;
    for (int i = blockIdx.x * blockDim.x + threadIdx.x; i < n4; i += stride) {
        const float4 v = *(const float4*)(src + 4 * (size_t)i);
        __half2 lo = __floats2half2_rn(v.x, v.y);
        __half2 hi = __floats2half2_rn(v.z, v.w);
        *(uint2*)(dst + 4 * (size_t)i) =
            make_uint2(*(uint32_t*)&lo, *(uint32_t*)&hi);
    }
}

// ---------------- routing --------------------------------------------------
__global__ void k_reset() {
    if (threadIdx.x < NE) sc_cnt[threadIdx.x] = 0;
}

__global__ void k_scan() {
    if (threadIdx.x == 0) {
        int a = 0;
        for (int e = 0; e < NE; e++) { sc_base[e] = a; a += sc_cnt[e]; }
    }
}

__global__ void k_gate(const float* __restrict__ x,
                       const float* __restrict__ gw) {
    __shared__ float red[256];
    __shared__ float lg[NE];
    const int t   = blockIdx.x;
    const int tid = threadIdx.x;
    const int e   = tid & 15;
    const int seg = tid >> 4;

    const float* xr = x  + (size_t)t * HH;
    const float* wr = gw + (size_t)e * HH;
    float s = 0.f;
    const int h0 = seg * 128;
#pragma unroll 8
    for (int h = h0; h < h0 + 128; h += 4) {
        float4 a = *(const float4*)(xr + h);
        float4 b = *(const float4*)(wr + h);
        s += a.x * b.x + a.y * b.y + a.z * b.z + a.w * b.w;
    }
    red[tid] = s;
    __syncthreads();
    if (tid < NE) {
        float tot = 0.f;
#pragma unroll
        for (int k = 0; k < 16; k++) tot += red[k * 16 + tid];
        lg[tid] = tot;
    }
    __syncthreads();
    if (tid == 0) {
        float mx = lg[0];
#pragma unroll
        for (int i = 1; i < NE; i++) mx = fmaxf(mx, lg[i]);
        float p[NE];
        float den = 0.f;
#pragma unroll
        for (int i = 0; i < NE; i++) { p[i] = expf(lg[i] - mx); den += p[i]; }
        const float inv = 1.f / den;
#pragma unroll
        for (int i = 0; i < NE; i++) p[i] *= inv;

        bool taken[NE];
#pragma unroll
        for (int i = 0; i < NE; i++) taken[i] = false;
        for (int j = 0; j < TOPK; j++) {
            int   be = 0;
            float bv = -1.f;
            for (int i = 0; i < NE; i++)
                if (!taken[i] && p[i] > bv) { bv = p[i]; be = i; }
            taken[be] = true;
            const int slot = atomicAdd(&sc_cnt[be], 1);
            sc_tok [be * TT + slot] = t;
            sc_prob[be * TT + slot] = p[be];
        }
    }
}

// ---------------- activations (fp32 in, fp16 out) ---------------------------
__global__ void k_silu_shared() {
    const int t = blockIdx.x;
    const float* r = sc_up   + (size_t)t * IS2;
    __half*      o = sc_acth + (size_t)t * ISH;
    for (int i = threadIdx.x; i < ISH; i += blockDim.x) {
        const float g = r[i];
        const float u = r[i + ISH];
        o[i] = __float2half_rn(u * g / (1.f + __expf(-g)));
    }
}

__global__ void k_silu_routed() {
    const int e = blockIdx.y;
    const int s = blockIdx.x;
    if (s >= sc_cnt[e]) return;
    const float w = sc_prob[e * TT + s];
    const size_t slot = (size_t)(sc_base[e] + s);
    const float* r = sc_up   + slot * I2;
    __half*      o = sc_acth + slot * ID;
    for (int i = threadIdx.x; i < ID; i += blockDim.x) {
        const float g = r[i];
        const float u = r[i + ID];
        o[i] = __float2half_rn(w * u * g / (1.f + __expf(-g)));
    }
}

// ---------------- FP16 tensor-core GEMM  C[M,N] = A[M,K] * B[N,K]^T ---------
// All-fp16 operands in global. 3-stage cp.async pipeline: global fp16 ->
// swizzled smem directly. Block 128x128, 8 warps (2m x 4n), warp tile 64x32,
// KT=32 halves/stage. Smem rows 64B = 4 x 16B kgroups, swizzled
// kg ^ ((row>>1)&3) (R14-verified with ldmatrix.x4). fp32 accumulate.
// Ring: compute cursor st = kt%3, refill cursor nx = (kt+2)%3 (the R15 NaN
// was refilling into st instead of nx).

__device__ __forceinline__ void hmma(float* c, const uint32_t* a, const uint32_t* b) {
    asm volatile(
        "mma.sync.aligned.m16n8k16.row.col.f32.f16.f16.f32 "
        "{%0,%1,%2,%3},{%4,%5,%6,%7},{%8,%9},{%0,%1,%2,%3};"
        : "+f"(c[0]), "+f"(c[1]), "+f"(c[2]), "+f"(c[3])
        : "r"(a[0]), "r"(a[1]), "r"(a[2]), "r"(a[3]), "r"(b[0]), "r"(b[1]));
}

__device__ __forceinline__ void ldmx4(uint32_t* r, uint32_t addr) {
    asm volatile(
        "ldmatrix.sync.aligned.m8n8.x4.shared.b16 {%0,%1,%2,%3}, [%4];"
        : "=r"(r[0]), "=r"(r[1]), "=r"(r[2]), "=r"(r[3]) : "r"(addr));
}

__device__ __forceinline__ void cpa16(uint32_t dst, const void* src, int srcsz) {
    asm volatile("cp.async.ca.shared.global [%0], [%1], 16, %2;"
                 :: "r"(dst), "l"(src), "r"(srcsz) : "memory");
}

#define KT    32
#define BM    128
#define BN    128
#define NTH   256
#define ROWB  64
#define STG   3
#define STAGEB 16384            // 8KB A + 8KB B per stage
#define SMEMB  (STG * STAGEB)   // 49152 = 48KB

template <bool GATH, bool SCAT>
__device__ __forceinline__ void gemm_body(
        const __half* __restrict__ A, int lda,
        const __half* __restrict__ B, int ldb,
        float* __restrict__ C, int ldc,
        int K, int M, const int* __restrict__ lst) {
    const int m0 = blockIdx.y * BM;
    if (m0 >= M) return;
    const int n0 = blockIdx.x * BN;

    __shared__ uint8_t sh[SMEMB];
    const uint32_t sb = (uint32_t)__cvta_generic_to_shared(sh);

    const int tid  = threadIdx.x;
    const int lane = tid & 31;
    const int wrp  = tid >> 5;
    const int wm = (wrp & 1) * 64;
    const int wn = (wrp >> 1) * 32;

    // staging: row = tid>>1; kgroups {2*(tid&1), 2*(tid&1)+1} (16B each)
    const int srow = tid >> 1;
    const int kg0  = (tid & 1) * 2;
    const int ssw  = (srow >> 1) & 3;

    const int  rA = m0 + srow;
    const bool ok = rA < M;
    int ar = 0;
    if (ok) ar = GATH ? lst[rA] : rA;
    const __half* ap = A + (size_t)ar * lda;
    const __half* bp = B + (size_t)(n0 + srow) * ldb;
    const int avsz = ok ? 16 : 0;

    const uint32_t dA0 = sb + srow * ROWB + (((kg0    ) ^ ssw) << 4);
    const uint32_t dA1 = sb + srow * ROWB + (((kg0 + 1) ^ ssw) << 4);
    const uint32_t dB0 = dA0 + 8192;
    const uint32_t dB1 = dA1 + 8192;

    const int nkt = K / KT;

#define ISSUE(kt, stg)                                                      \
    do {                                                                    \
        if ((kt) < nkt) {                                                   \
            const uint32_t so = (uint32_t)((stg) * STAGEB);                 \
            const __half* a_ = ap + (kt) * KT + kg0 * 8;                    \
            const __half* b_ = bp + (kt) * KT + kg0 * 8;                    \
            cpa16(dA0 + so, a_,     avsz);                                  \
            cpa16(dA1 + so, a_ + 8, avsz);                                  \
            cpa16(dB0 + so, b_,     16);                                    \
            cpa16(dB1 + so, b_ + 8, 16);                                    \
        }                                                                   \
        asm volatile("cp.async.commit_group;" ::: "memory");                \
    } while (0)

    float acc[4][4][4];
#pragma unroll
    for (int mi = 0; mi < 4; mi++)
#pragma unroll
        for (int ni = 0; ni < 4; ni++)
#pragma unroll
            for (int i = 0; i < 4; i++) acc[mi][ni][i] = 0.f;

    // fragment addresses (R14-verified mapping)
    const int rFA = wm + (lane & 15);
    const int swA = (rFA >> 1) & 3;
    const int hiA = lane >> 4;
    const int rFB = wn + ((lane >> 4) << 3) + (lane & 7);
    const int swB = (rFB >> 1) & 3;
    const int seB = (lane >> 3) & 1;

    const int q  = lane >> 2;
    const int kb = lane & 3;

    ISSUE(0, 0);
    ISSUE(1, 1);

    int st = 0;          // compute cursor: kt % 3
    int nx = 2;          // refill cursor: (kt + 2) % 3
    for (int kt = 0; kt < nkt; kt++) {
        asm volatile("cp.async.wait_group %0;" :: "n"(1) : "memory");
        __syncthreads();

        const uint32_t bA = sb + st * STAGEB;
        const uint32_t bB = bA + 8192;

#pragma unroll
        for (int s = 0; s < 2; s++) {
            uint32_t fa[4][4], fb[2][4];
#pragma unroll
            for (int mi = 0; mi < 4; mi++)
                ldmx4(fa[mi], bA + (rFA + mi * 16) * ROWB
                              + (((2 * s + hiA) ^ swA) << 4));
#pragma unroll
            for (int j = 0; j < 2; j++)
                ldmx4(fb[j], bB + (rFB + 16 * j) * ROWB
                             + (((2 * s + seB) ^ swB) << 4));
#pragma unroll
            for (int mi = 0; mi < 4; mi++)
#pragma unroll
                for (int ni = 0; ni < 4; ni++) {
                    uint32_t bb[2] = { (ni & 1) ? fb[ni >> 1][2] : fb[ni >> 1][0],
                                       (ni & 1) ? fb[ni >> 1][3] : fb[ni >> 1][1] };
                    hmma(acc[mi][ni], fa[mi], bb);
                }
        }

        __syncthreads();   // stage nx ( == (kt-1)%3 ) fully consumed before refill
        ISSUE(kt + 2, nx);
        st = (st + 1 == STG) ? 0 : st + 1;
        nx = (nx + 1 == STG) ? 0 : nx + 1;
    }

    // epilogue
#pragma unroll
    for (int mi = 0; mi < 4; mi++) {
        const int rlo = m0 + wm + mi * 16 + q;
        const int rhi = rlo + 8;
#pragma unroll
        for (int ni = 0; ni < 4; ni++) {
            const int col = n0 + wn + ni * 8 + 2 * kb;
            if (rlo < M) {
                const int cr = SCAT ? lst[rlo] : rlo;
                float* cp = C + (size_t)cr * ldc + col;
                if (SCAT) {
                    atomicAdd(cp,     acc[mi][ni][0]);
                    atomicAdd(cp + 1, acc[mi][ni][1]);
                } else {
                    *(float2*)cp = make_float2(acc[mi][ni][0], acc[mi][ni][1]);
                }
            }
            if (rhi < M) {
                const int cr = SCAT ? lst[rhi] : rhi;
                float* cp = C + (size_t)cr * ldc + col;
                if (SCAT) {
                    atomicAdd(cp,     acc[mi][ni][2]);
                    atomicAdd(cp + 1, acc[mi][ni][3]);
                } else {
                    *(float2*)cp = make_float2(acc[mi][ni][2], acc[mi][ni][3]);
                }
            }
        }
    }
#undef ISSUE
}

// ---------------- GEMM entry points -----------------------------------------
__global__ void __launch_bounds__(NTH, 2)
k_ffn_up() {
    gemm_body<false, false>(sc_xh, HH, sc_sw1h, HH, sc_up, IS2, HH, TT, nullptr);
}

__global__ void __launch_bounds__(NTH, 2)
k_ffn_down(float* __restrict__ out) {
    gemm_body<false, false>(sc_acth, ISH, sc_sw2h, ISH, out, HH, ISH, TT, nullptr);
}

__global__ void __launch_bounds__(NTH, 2)
k_moe_up() {
    const int e = blockIdx.z;
    gemm_body<true, false>(
        sc_xh, HH,
        sc_w1h + (size_t)e * I2 * HH, HH,
        sc_up + (size_t)sc_base[e] * I2, I2,
        HH, sc_cnt[e], sc_tok + e * TT);
}

__global__ void __launch_bounds__(NTH, 2)
k_moe_down(float* __restrict__ out) {
    const int e = blockIdx.z;
    gemm_body<false, true>(
        sc_acth + (size_t)sc_base[e] * ID, ID,
        sc_w2h + (size_t)e * HH * ID, ID,
        out, HH,
        ID, sc_cnt[e], sc_tok + e * TT);
}

// ---------------- launcher (kernel launches only) ---------------------------
extern "C" void kernel_launch(void* const* d_in, const int* in_sizes, int n_in,
                              void* d_out, int out_size) {
    const float* x   = (const float*)d_in[0];
    const float* gw  = (const float*)d_in[1];
    const float* w1  = (const float*)d_in[2];
    const float* w2  = (const float*)d_in[3];
    const float* sw1 = (const float*)d_in[4];
    const float* sw2 = (const float*)d_in[5];
    float* out = (float*)d_out;
    (void)in_sizes; (void)n_in; (void)out_size;

    __half *xh, *w1h, *w2h, *sw1h, *sw2h;
    cudaGetSymbolAddress((void**)&xh,   sc_xh);
    cudaGetSymbolAddress((void**)&w1h,  sc_w1h);
    cudaGetSymbolAddress((void**)&w2h,  sc_w2h);
    cudaGetSymbolAddress((void**)&sw1h, sc_sw1h);
    cudaGetSymbolAddress((void**)&sw2h, sc_sw2h);

    // 0) fp16 conversions
    k_cvt<<<1184, 256>>>(x,   xh,   (TT * HH) / 4);
    k_cvt<<<1184, 256>>>(sw1, sw1h, (IS2 * HH) / 4);
    k_cvt<<<1184, 256>>>(sw2, sw2h, (HH * ISH) / 4);
    k_cvt<<<2368, 256>>>(w1,  w1h,  (NE * I2 * HH) / 4);
    k_cvt<<<2368, 256>>>(w2,  w2h,  (NE * HH * ID) / 4);

    // 1) routing
    k_reset<<<1, 32>>>();
    k_gate<<<TT, 256>>>(x, gw);
    k_scan<<<1, 32>>>();

    // 2) shared FFN
    k_ffn_up<<<dim3(IS2 / BN, TT / BM, 1), NTH>>>();
    k_silu_shared<<<TT, 256>>>();
    k_ffn_down<<<dim3(HH / BN, TT / BM, 1), NTH>>>(out);

    // 3) routed path
    k_moe_up<<<dim3(I2 / BN, TT / BM, NE), NTH>>>();
    k_silu_routed<<<dim3(TT, NE), 256>>>();
    k_moe_down<<<dim3(HH / BN, TT / BM, NE), NTH>>>(out);
}

// round 17
// speedup vs baseline: 2.1796x; 1.0238x over previous
#include <cuda_runtime.h>
#include <cuda_fp16.h>
#include <cstdint>
#include <cstddef>

// Problem shape
#define TT   2048
#define HH   2048
#define NE   16
#define TOPK 6
#define ID   1408
#define I2   2816
#define ISH  2816
#define IS2  5632
#define NSLOT (TT * TOPK)

// ---------------- device scratch -------------------------------------------
__device__ __half sc_acth[(size_t)NSLOT * ID];    // 34.6 MB fp16 activations (head = shared)
__device__ __half sc_xh  [(size_t)TT * HH];       //  8.4 MB
__device__ __half sc_w1h [(size_t)NE * I2 * HH];  // 184.5 MB
__device__ __half sc_w2h [(size_t)NE * HH * ID];  //  92.3 MB
__device__ __half sc_sw1h[(size_t)IS2 * HH];      //  23.1 MB
__device__ __half sc_sw2h[(size_t)HH * ISH];      //  11.5 MB
__device__ int    sc_cnt [NE];
__device__ int    sc_base[NE];
__device__ int    sc_tok [NE * TT];
__device__ float  sc_prob[NE * TT];

// ---------------- f32 -> f16 conversion ------------------------------------
__global__ void k_cvt(const float* __restrict__ src, __half* __restrict__ dst,
                      int n4) {
    const int stride = gridDim.x * blockDim.x;
    for (int i = blockIdx.x * blockDim.x + threadIdx.x; i < n4; i += stride) {
        const float4 v = *(const float4*)(src + 4 * (size_t)i);
        __half2 lo = __floats2half2_rn(v.x, v.y);
        __half2 hi = __floats2half2_rn(v.z, v.w);
        *(uint2*)(dst + 4 * (size_t)i) =
            make_uint2(*(uint32_t*)&lo, *(uint32_t*)&hi);
    }
}

// ---------------- routing --------------------------------------------------
__global__ void k_reset() {
    if (threadIdx.x < NE) sc_cnt[threadIdx.x] = 0;
}

__global__ void k_scan() {
    if (threadIdx.x == 0) {
        int a = 0;
        for (int e = 0; e < NE; e++) { sc_base[e] = a; a += sc_cnt[e]; }
    }
}

__global__ void k_gate(const float* __restrict__ x,
                       const float* __restrict__ gw) {
    __shared__ float red[256];
    __shared__ float lg[NE];
    const int t   = blockIdx.x;
    const int tid = threadIdx.x;
    const int e   = tid & 15;
    const int seg = tid >> 4;

    const float* xr = x  + (size_t)t * HH;
    const float* wr = gw + (size_t)e * HH;
    float s = 0.f;
    const int h0 = seg * 128;
#pragma unroll 8
    for (int h = h0; h < h0 + 128; h += 4) {
        float4 a = *(const float4*)(xr + h);
        float4 b = *(const float4*)(wr + h);
        s += a.x * b.x + a.y * b.y + a.z * b.z + a.w * b.w;
    }
    red[tid] = s;
    __syncthreads();
    if (tid < NE) {
        float tot = 0.f;
#pragma unroll
        for (int k = 0; k < 16; k++) tot += red[k * 16 + tid];
        lg[tid] = tot;
    }
    __syncthreads();
    if (tid == 0) {
        float mx = lg[0];
#pragma unroll
        for (int i = 1; i < NE; i++) mx = fmaxf(mx, lg[i]);
        float p[NE];
        float den = 0.f;
#pragma unroll
        for (int i = 0; i < NE; i++) { p[i] = expf(lg[i] - mx); den += p[i]; }
        const float inv = 1.f / den;
#pragma unroll
        for (int i = 0; i < NE; i++) p[i] *= inv;

        bool taken[NE];
#pragma unroll
        for (int i = 0; i < NE; i++) taken[i] = false;
        for (int j = 0; j < TOPK; j++) {
            int   be = 0;
            float bv = -1.f;
            for (int i = 0; i < NE; i++)
                if (!taken[i] && p[i] > bv) { bv = p[i]; be = i; }
            taken[be] = true;
            const int slot = atomicAdd(&sc_cnt[be], 1);
            sc_tok [be * TT + slot] = t;
            sc_prob[be * TT + slot] = p[be];
        }
    }
}

// ---------------- FP16 tensor-core GEMM ------------------------------------
// C[M,N] = A[M,K] * B[N,K]^T, all fp16 operands, fp32 accumulate.
// 3-stage cp.async pipeline into swizzled smem (R16-verified). Block 128x128,
// 8 warps (2m x 4n), warp tile 64x32, KT=32 halves/stage, 48 KB static smem,
// 2 CTAs/SM.
// FUSE mode (up-projections): logical B row 2j -> W[j] (gate), 2j+1 ->
// W[j+halfN] (up), so each epilogue thread's (c, c+1) register pair is
// (gate_j, up_j); computes w * u * silu(g) on fp32 accumulators and writes
// ONE fp16 to ACT[row * halfN + j]. Kills the gate_up buffer + silu kernels.

__device__ __forceinline__ void hmma(float* c, const uint32_t* a, const uint32_t* b) {
    asm volatile(
        "mma.sync.aligned.m16n8k16.row.col.f32.f16.f16.f32 "
        "{%0,%1,%2,%3},{%4,%5,%6,%7},{%8,%9},{%0,%1,%2,%3};"
        : "+f"(c[0]), "+f"(c[1]), "+f"(c[2]), "+f"(c[3])
        : "r"(a[0]), "r"(a[1]), "r"(a[2]), "r"(a[3]), "r"(b[0]), "r"(b[1]));
}

__device__ __forceinline__ void ldmx4(uint32_t* r, uint32_t addr) {
    asm volatile(
        "ldmatrix.sync.aligned.m8n8.x4.shared.b16 {%0,%1,%2,%3}, [%4];"
        : "=r"(r[0]), "=r"(r[1]), "=r"(r[2]), "=r"(r[3]) : "r"(addr));
}

__device__ __forceinline__ void cpa16(uint32_t dst, const void* src, int srcsz) {
    asm volatile("cp.async.ca.shared.global [%0], [%1], 16, %2;"
                 :: "r"(dst), "l"(src), "r"(srcsz) : "memory");
}

#define KT    32
#define BM    128
#define BN    128
#define NTH   256
#define ROWB  64
#define STG   3
#define STAGEB 16384
#define SMEMB  (STG * STAGEB)   // 48 KB

template <bool GATH, bool SCAT, bool FUSE>
__device__ __forceinline__ void gemm_body(
        const __half* __restrict__ A, int lda,
        const __half* __restrict__ B, int ldb,
        float* __restrict__ C, int ldc,
        __half* __restrict__ ACT, int halfN,
        const float* __restrict__ prob,
        int K, int M, const int* __restrict__ lst) {
    const int m0 = blockIdx.y * BM;
    if (m0 >= M) return;
    const int n0 = blockIdx.x * BN;

    __shared__ uint8_t sh[SMEMB];
    const uint32_t sb = (uint32_t)__cvta_generic_to_shared(sh);

    const int tid  = threadIdx.x;
    const int lane = tid & 31;
    const int wrp  = tid >> 5;
    const int wm = (wrp & 1) * 64;
    const int wn = (wrp >> 1) * 32;

    // staging: row = tid>>1; kgroups {2*(tid&1), 2*(tid&1)+1}
    const int srow = tid >> 1;
    const int kg0  = (tid & 1) * 2;
    const int ssw  = (srow >> 1) & 3;

    const int  rA = m0 + srow;
    const bool ok = rA < M;
    int ar = 0;
    if (ok) ar = GATH ? lst[rA] : rA;
    const __half* ap = A + (size_t)ar * lda;
    // B row mapping: FUSE interleaves gate/up rows
    const int lrow = n0 + srow;
    const size_t brow = FUSE ? ((size_t)(lrow >> 1) + (size_t)(lrow & 1) * halfN)
                             : (size_t)lrow;
    const __half* bp = B + brow * ldb;
    const int avsz = ok ? 16 : 0;

    const uint32_t dA0 = sb + srow * ROWB + (((kg0    ) ^ ssw) << 4);
    const uint32_t dA1 = sb + srow * ROWB + (((kg0 + 1) ^ ssw) << 4);
    const uint32_t dB0 = dA0 + 8192;
    const uint32_t dB1 = dA1 + 8192;

    const int nkt = K / KT;

#define ISSUE(kt, stg)                                                      \
    do {                                                                    \
        if ((kt) < nkt) {                                                   \
            const uint32_t so = (uint32_t)((stg) * STAGEB);                 \
            const __half* a_ = ap + (kt) * KT + kg0 * 8;                    \
            const __half* b_ = bp + (kt) * KT + kg0 * 8;                    \
            cpa16(dA0 + so, a_,     avsz);                                  \
            cpa16(dA1 + so, a_ + 8, avsz);                                  \
            cpa16(dB0 + so, b_,     16);                                    \
            cpa16(dB1 + so, b_ + 8, 16);                                    \
        }                                                                   \
        asm volatile("cp.async.commit_group;" ::: "memory");                \
    } while (0)

    float acc[4][4][4];
#pragma unroll
    for (int mi = 0; mi < 4; mi++)
#pragma unroll
        for (int ni = 0; ni < 4; ni++)
#pragma unroll
            for (int i = 0; i < 4; i++) acc[mi][ni][i] = 0.f;

    const int rFA = wm + (lane & 15);
    const int swA = (rFA >> 1) & 3;
    const int hiA = lane >> 4;
    const int rFB = wn + ((lane >> 4) << 3) + (lane & 7);
    const int swB = (rFB >> 1) & 3;
    const int seB = (lane >> 3) & 1;

    const int q  = lane >> 2;
    const int kb = lane & 3;

    ISSUE(0, 0);
    ISSUE(1, 1);

    int st = 0;          // compute cursor: kt % 3
    int nx = 2;          // refill cursor: (kt + 2) % 3
    for (int kt = 0; kt < nkt; kt++) {
        asm volatile("cp.async.wait_group %0;" :: "n"(1) : "memory");
        __syncthreads();

        const uint32_t bA = sb + st * STAGEB;
        const uint32_t bB = bA + 8192;

#pragma unroll
        for (int s = 0; s < 2; s++) {
            uint32_t fa[4][4], fb[2][4];
#pragma unroll
            for (int mi = 0; mi < 4; mi++)
                ldmx4(fa[mi], bA + (rFA + mi * 16) * ROWB
                              + (((2 * s + hiA) ^ swA) << 4));
#pragma unroll
            for (int j = 0; j < 2; j++)
                ldmx4(fb[j], bB + (rFB + 16 * j) * ROWB
                             + (((2 * s + seB) ^ swB) << 4));
#pragma unroll
            for (int mi = 0; mi < 4; mi++)
#pragma unroll
                for (int ni = 0; ni < 4; ni++) {
                    uint32_t bb[2] = { (ni & 1) ? fb[ni >> 1][2] : fb[ni >> 1][0],
                                       (ni & 1) ? fb[ni >> 1][3] : fb[ni >> 1][1] };
                    hmma(acc[mi][ni], fa[mi], bb);
                }
        }

        __syncthreads();
        ISSUE(kt + 2, nx);
        st = (st + 1 == STG) ? 0 : st + 1;
        nx = (nx + 1 == STG) ? 0 : nx + 1;
    }

    // epilogue
#pragma unroll
    for (int mi = 0; mi < 4; mi++) {
        const int rlo = m0 + wm + mi * 16 + q;
        const int rhi = rlo + 8;
#pragma unroll
        for (int ni = 0; ni < 4; ni++) {
            if (FUSE) {
                // (c, c+1) = (gate_j, up_j); j = (n0+wn+ni*8)/2 + kb
                const int j = ((n0 + wn + ni * 8) >> 1) + kb;
                if (rlo < M) {
                    const float w = prob ? prob[rlo] : 1.f;
                    const float g = acc[mi][ni][0], u = acc[mi][ni][1];
                    ACT[(size_t)rlo * halfN + j] =
                        __float2half_rn(w * u * g / (1.f + __expf(-g)));
                }
                if (rhi < M) {
                    const float w = prob ? prob[rhi] : 1.f;
                    const float g = acc[mi][ni][2], u = acc[mi][ni][3];
                    ACT[(size_t)rhi * halfN + j] =
                        __float2half_rn(w * u * g / (1.f + __expf(-g)));
                }
            } else {
                const int col = n0 + wn + ni * 8 + 2 * kb;
                if (rlo < M) {
                    const int cr = SCAT ? lst[rlo] : rlo;
                    float* cp = C + (size_t)cr * ldc + col;
                    if (SCAT) {
                        atomicAdd(cp,     acc[mi][ni][0]);
                        atomicAdd(cp + 1, acc[mi][ni][1]);
                    } else {
                        *(float2*)cp = make_float2(acc[mi][ni][0], acc[mi][ni][1]);
                    }
                }
                if (rhi < M) {
                    const int cr = SCAT ? lst[rhi] : rhi;
                    float* cp = C + (size_t)cr * ldc + col;
                    if (SCAT) {
                        atomicAdd(cp,     acc[mi][ni][2]);
                        atomicAdd(cp + 1, acc[mi][ni][3]);
                    } else {
                        *(float2*)cp = make_float2(acc[mi][ni][2], acc[mi][ni][3]);
                    }
                }
            }
        }
    }
#undef ISSUE
}

// ---------------- GEMM entry points -----------------------------------------
__global__ void __launch_bounds__(NTH, 2)
k_ffn_up() {   // fused: writes fp16 shared activations (head of sc_acth, stride ISH)
    gemm_body<false, false, true>(sc_xh, HH, sc_sw1h, HH,
                                  nullptr, 0, sc_acth, ISH, nullptr,
                                  HH, TT, nullptr);
}

__global__ void __launch_bounds__(NTH, 2)
k_ffn_down(float* __restrict__ out) {
    gemm_body<false, false, false>(sc_acth, ISH, sc_sw2h, ISH,
                                   out, HH, nullptr, 0, nullptr,
                                   ISH, TT, nullptr);
}

__global__ void __launch_bounds__(NTH, 2)
k_moe_up() {   // fused: writes weighted fp16 routed activations
    const int e = blockIdx.z;
    gemm_body<true, false, true>(
        sc_xh, HH,
        sc_w1h + (size_t)e * I2 * HH, HH,
        nullptr, 0,
        sc_acth + (size_t)sc_base[e] * ID, ID,
        sc_prob + e * TT,
        HH, sc_cnt[e], sc_tok + e * TT);
}

__global__ void __launch_bounds__(NTH, 2)
k_moe_down(float* __restrict__ out) {
    const int e = blockIdx.z;
    gemm_body<false, true, false>(
        sc_acth + (size_t)sc_base[e] * ID, ID,
        sc_w2h + (size_t)e * HH * ID, ID,
        out, HH, nullptr, 0, nullptr,
        ID, sc_cnt[e], sc_tok + e * TT);
}

// ---------------- launcher (kernel launches only) ---------------------------
extern "C" void kernel_launch(void* const* d_in, const int* in_sizes, int n_in,
                              void* d_out, int out_size) {
    const float* x   = (const float*)d_in[0];
    const float* gw  = (const float*)d_in[1];
    const float* w1  = (const float*)d_in[2];
    const float* w2  = (const float*)d_in[3];
    const float* sw1 = (const float*)d_in[4];
    const float* sw2 = (const float*)d_in[5];
    float* out = (float*)d_out;
    (void)in_sizes; (void)n_in; (void)out_size;

    __half *xh, *w1h, *w2h, *sw1h, *sw2h;
    cudaGetSymbolAddress((void**)&xh,   sc_xh);
    cudaGetSymbolAddress((void**)&w1h,  sc_w1h);
    cudaGetSymbolAddress((void**)&w2h,  sc_w2h);
    cudaGetSymbolAddress((void**)&sw1h, sc_sw1h);
    cudaGetSymbolAddress((void**)&sw2h, sc_sw2h);

    // 0) fp16 conversions
    k_cvt<<<1184, 256>>>(x,   xh,   (TT * HH) / 4);
    k_cvt<<<1184, 256>>>(sw1, sw1h, (IS2 * HH) / 4);
    k_cvt<<<1184, 256>>>(sw2, sw2h, (HH * ISH) / 4);
    k_cvt<<<2368, 256>>>(w1,  w1h,  (NE * I2 * HH) / 4);
    k_cvt<<<2368, 256>>>(w2,  w2h,  (NE * HH * ID) / 4);

    // 1) routing
    k_reset<<<1, 32>>>();
    k_gate<<<TT, 256>>>(x, gw);
    k_scan<<<1, 32>>>();

    // 2) shared FFN (silu fused into up-GEMM epilogue)
    k_ffn_up<<<dim3(IS2 / BN, TT / BM, 1), NTH>>>();
    k_ffn_down<<<dim3(HH / BN, TT / BM, 1), NTH>>>(out);

    // 3) routed path (weighted silu fused into up-GEMM epilogue)
    k_moe_up<<<dim3(I2 / BN, TT / BM, NE), NTH>>>();
    k_moe_down<<<dim3(HH / BN, TT / BM, NE), NTH>>>(out);
}